// round 4
// baseline (speedup 1.0000x reference)
#include <cuda_runtime.h>
#include <math.h>

#define BB 32
#define NN 512
#define NH 8
#define NWRD 16   // 512/32 bitmask words per adjacency row

// ---------------- scratch (device globals; no allocations) ----------------
__device__ unsigned g_bits[BB*NN*NWRD];          // adjacency bitmask
__device__ float g_Wh1[BB*NN*512];               // layer1 per-head projections (concat)
__device__ float g_x1 [BB*NN*512];               // layer1 output (ELU'd concat)
__device__ float g_Wh2[BB*NN*128];               // layer2 projection
__device__ float g_att2[BB*NN*128];              // layer2 GAT output
// per-(node,head) layer1 score factors (Aa/Ca are PRE-NORMALIZED by rowsum Z)
__device__ float g_s1a[BB*NN*NH], g_s2a[BB*NN*NH];
__device__ float g_Aa [BB*NN*NH], g_Ca [BB*NN*NH];
__device__ float g_Pa [BB*NN*NH], g_Qa [BB*NN*NH];
// per-node layer2 score factors
__device__ float g_s1b[BB*NN], g_s2b[BB*NN];
__device__ float g_Ab [BB*NN], g_Cb [BB*NN];
__device__ float g_Pb [BB*NN], g_Qb [BB*NN];

// ---------------- adjacency bitmask ----------------
__global__ void k_bits(const int* __restrict__ adj) {
  int row = blockIdx.x;                      // b*NN + i
  const int* a = adj + (size_t)row*NN;
  int lane = threadIdx.x & 31, w = threadIdx.x >> 5;
  for (int c = w; c < NWRD; c += 2) {
    unsigned m = __ballot_sync(0xffffffffu, a[c*32 + lane] > 0);
    if (lane == 0) g_bits[row*NWRD + c] = m;
  }
}

// ---------------- projection SGEMM: C[M,*] = A[M,K] @ B[K,*], 64x64 tiles ----------------
// MODE 1: A=graph_inf (K=128), B=W_heads [h][f][o] -> col h*64+o, C=g_Wh1 (ldc 512)
// MODE 2: A=g_x1 (K=512),      B=W_out [512,128],                 C=g_Wh2 (ldc 128)
template<int K, int MODE>
__global__ __launch_bounds__(256) void k_proj(const float* __restrict__ Ain,
                                              const float* __restrict__ Bsrc) {
  __shared__ float As[16][68];
  __shared__ float Bs[16][68];
  const float* A = (MODE==1) ? Ain : g_x1;
  float* C = (MODE==1) ? g_Wh1 : g_Wh2;
  const int ldc = (MODE==1) ? 512 : 128;
  int m0 = blockIdx.x*64, n0 = blockIdx.y*64;
  int tid = threadIdx.x, tx = tid & 15, ty = tid >> 4;
  float acc[4][4] = {};
  for (int k0 = 0; k0 < K; k0 += 16) {
    {
      int m = tid >> 2, kq = (tid & 3) * 4;
      float4 v = *(const float4*)(A + (size_t)(m0+m)*K + k0 + kq);
      As[kq+0][m]=v.x; As[kq+1][m]=v.y; As[kq+2][m]=v.z; As[kq+3][m]=v.w;
    }
    {
      int k = tid >> 4, n4 = (tid & 15) * 4;
      float4 v;
      if (MODE==1) {
        int h = n0 >> 6;   // BN=64 aligned to head boundary
        v = *(const float4*)(Bsrc + ((size_t)h*128 + k0 + k)*64 + n4);
      } else {
        v = *(const float4*)(Bsrc + (size_t)(k0+k)*128 + n0 + n4);
      }
      *(float4*)&Bs[k][n4] = v;
    }
    __syncthreads();
#pragma unroll
    for (int kk = 0; kk < 16; kk++) {
      float4 av = *(float4*)&As[kk][ty*4];
      float4 bv = *(float4*)&Bs[kk][tx*4];
      float a_[4] = {av.x,av.y,av.z,av.w};
      float b_[4] = {bv.x,bv.y,bv.z,bv.w};
#pragma unroll
      for (int i=0;i<4;i++)
#pragma unroll
        for (int j=0;j<4;j++) acc[i][j] = fmaf(a_[i], b_[j], acc[i][j]);
    }
    __syncthreads();
  }
#pragma unroll
  for (int i=0;i<4;i++) {
    float4 v = make_float4(acc[i][0],acc[i][1],acc[i][2],acc[i][3]);
    *(float4*)(C + (size_t)(m0 + ty*4 + i)*ldc + n0 + tx*4) = v;
  }
}

// ---------------- layer1 scores: s1,s2 per (node,head) + P,Q ----------------
__global__ __launch_bounds__(256) void k_scores1(const float* __restrict__ a_heads) {
  int row = blockIdx.x;                    // b*NN + n
  int w = threadIdx.x >> 5, l = threadIdx.x & 31;   // warp = head
  const float* wh = g_Wh1 + (size_t)row*512 + w*64;
  const float* ah = a_heads + w*128;
  float s1 = wh[l]*ah[l]    + wh[l+32]*ah[l+32];
  float s2 = wh[l]*ah[64+l] + wh[l+32]*ah[96+l];
  for (int d=16; d; d>>=1) {
    s1 += __shfl_xor_sync(0xffffffffu, s1, d);
    s2 += __shfl_xor_sync(0xffffffffu, s2, d);
  }
  if (l == 0) {
    int idx = row*NH + w;
    g_s1a[idx] = s1; g_s2a[idx] = s2;
    g_Pa[idx] = __expf(s2); g_Qa[idx] = __expf(0.2f*s2);
  }
}

// ---------------- layer1 rowmax + rowsum -> normalized A/Z, C/Z ----------------
__global__ __launch_bounds__(256) void k_rowmax1() {
  __shared__ float red[8][8];
  __shared__ float redSP[8][8], redSQ[8][8];
  __shared__ float sA[8], sC[8], sT[8];
  int row = blockIdx.x;                    // b*NN + i
  int b = row >> 9;
  int tid = threadIdx.x, lane = tid & 31, w = tid >> 5;
  float m[NH];
#pragma unroll
  for (int h=0;h<NH;h++) m[h] = -INFINITY;
  for (int j = tid; j < NN; j += 256) {
    unsigned wrd = g_bits[row*NWRD + (j>>5)];
    if ((wrd >> (j&31)) & 1u) {
      const float* s2 = g_s2a + (size_t)(b*NN + j)*NH;
      float4 v0 = *(const float4*)s2;
      float4 v1 = *(const float4*)(s2+4);
      m[0]=fmaxf(m[0],v0.x); m[1]=fmaxf(m[1],v0.y); m[2]=fmaxf(m[2],v0.z); m[3]=fmaxf(m[3],v0.w);
      m[4]=fmaxf(m[4],v1.x); m[5]=fmaxf(m[5],v1.y); m[6]=fmaxf(m[6],v1.z); m[7]=fmaxf(m[7],v1.w);
    }
  }
#pragma unroll
  for (int h=0;h<NH;h++)
    for (int d=16; d; d>>=1) m[h] = fmaxf(m[h], __shfl_xor_sync(0xffffffffu, m[h], d));
  if (lane == 0) {
#pragma unroll
    for (int h=0;h<NH;h++) red[h][w] = m[h];
  }
  __syncthreads();
  if (tid < 8) {
    float M = red[tid][0];
    for (int ww=1; ww<8; ww++) M = fmaxf(M, red[tid][ww]);
    float s1 = g_s1a[row*NH + tid];
    float A = 0.f, Cc = 0.f;
    if (M > -INFINITY) {
      float e = s1 + M;
      float mm = (e > 0.f) ? e : 0.2f*e;      // rowmax of leakyrelu
      A  = __expf(s1 - mm);
      Cc = __expf(0.2f*s1 - mm);
    }
    sA[tid] = A; sC[tid] = Cc; sT[tid] = -s1;
  }
  __syncthreads();
  // pass 2: rowsum pieces SP = sum P_j (s2_j > -s1), SQ = sum Q_j (else), per head
  float thr[NH];
#pragma unroll
  for (int h=0;h<NH;h++) thr[h] = sT[h];
  float sp[NH] = {}, sq[NH] = {};
  for (int j = tid; j < NN; j += 256) {
    unsigned wrd = g_bits[row*NWRD + (j>>5)];
    if ((wrd >> (j&31)) & 1u) {
      size_t base = (size_t)(b*NN + j)*NH;
      float4 s20 = *(const float4*)(g_s2a + base);
      float4 s21 = *(const float4*)(g_s2a + base + 4);
      float4 p0  = *(const float4*)(g_Pa  + base);
      float4 p1  = *(const float4*)(g_Pa  + base + 4);
      float4 q0  = *(const float4*)(g_Qa  + base);
      float4 q1  = *(const float4*)(g_Qa  + base + 4);
      float s2v[8] = {s20.x,s20.y,s20.z,s20.w,s21.x,s21.y,s21.z,s21.w};
      float pv [8] = {p0.x,p0.y,p0.z,p0.w,p1.x,p1.y,p1.z,p1.w};
      float qv [8] = {q0.x,q0.y,q0.z,q0.w,q1.x,q1.y,q1.z,q1.w};
#pragma unroll
      for (int h=0;h<NH;h++) {
        if (s2v[h] > thr[h]) sp[h] += pv[h]; else sq[h] += qv[h];
      }
    }
  }
#pragma unroll
  for (int h=0;h<NH;h++)
    for (int d=16; d; d>>=1) {
      sp[h] += __shfl_xor_sync(0xffffffffu, sp[h], d);
      sq[h] += __shfl_xor_sync(0xffffffffu, sq[h], d);
    }
  if (lane == 0) {
#pragma unroll
    for (int h=0;h<NH;h++) { redSP[h][w] = sp[h]; redSQ[h][w] = sq[h]; }
  }
  __syncthreads();
  if (tid < 8) {
    float SP = 0.f, SQ = 0.f;
    for (int ww=0; ww<8; ww++) { SP += redSP[tid][ww]; SQ += redSQ[tid][ww]; }
    float A = sA[tid], Cc = sC[tid];
    float Z = A*SP + Cc*SQ;
    float zi = (Z > 0.f) ? 1.f/Z : 0.f;
    g_Aa[row*NH + tid] = A*zi;
    g_Ca[row*NH + tid] = Cc*zi;
  }
}

// ---------------- layer2 scores ----------------
__global__ __launch_bounds__(256) void k_scores2(const float* __restrict__ a_out) {
  int row = blockIdx.x*8 + (threadIdx.x >> 5);
  int l = threadIdx.x & 31;
  const float* wh = g_Wh2 + (size_t)row*128;
  float s1=0.f, s2=0.f;
#pragma unroll
  for (int r=0;r<4;r++){
    int o=l+r*32; float x=wh[o];
    s1 = fmaf(x, a_out[o], s1);
    s2 = fmaf(x, a_out[128+o], s2);
  }
  for (int d=16; d; d>>=1) {
    s1 += __shfl_xor_sync(0xffffffffu, s1, d);
    s2 += __shfl_xor_sync(0xffffffffu, s2, d);
  }
  if (l==0) {
    g_s1b[row]=s1; g_s2b[row]=s2;
    g_Pb[row]=__expf(s2); g_Qb[row]=__expf(0.2f*s2);
  }
}

__global__ __launch_bounds__(256) void k_rowmax2() {
  __shared__ float red[8], redSP[8], redSQ[8];
  __shared__ float sAb, sCb, sTb;
  int row = blockIdx.x;
  int b = row >> 9;
  int tid = threadIdx.x, lane = tid & 31, w = tid >> 5;
  float m = -INFINITY;
  for (int j = tid; j < NN; j += 256) {
    unsigned wrd = g_bits[row*NWRD + (j>>5)];
    if ((wrd >> (j&31)) & 1u) m = fmaxf(m, g_s2b[b*NN + j]);
  }
  for (int d=16; d; d>>=1) m = fmaxf(m, __shfl_xor_sync(0xffffffffu, m, d));
  if (lane == 0) red[w] = m;
  __syncthreads();
  if (tid == 0) {
    float M = red[0];
    for (int ww=1; ww<8; ww++) M = fmaxf(M, red[ww]);
    float s1 = g_s1b[row];
    float A = 0.f, Cc = 0.f;
    if (M > -INFINITY) {
      float e = s1 + M;
      float mm = (e > 0.f) ? e : 0.2f*e;
      A  = __expf(s1 - mm);
      Cc = __expf(0.2f*s1 - mm);
    }
    sAb = A; sCb = Cc; sTb = -s1;
  }
  __syncthreads();
  float thr = sTb;
  float sp = 0.f, sq = 0.f;
  for (int j = tid; j < NN; j += 256) {
    unsigned wrd = g_bits[row*NWRD + (j>>5)];
    if ((wrd >> (j&31)) & 1u) {
      float s2 = g_s2b[b*NN + j];
      if (s2 > thr) sp += g_Pb[b*NN + j]; else sq += g_Qb[b*NN + j];
    }
  }
  for (int d=16; d; d>>=1) {
    sp += __shfl_xor_sync(0xffffffffu, sp, d);
    sq += __shfl_xor_sync(0xffffffffu, sq, d);
  }
  if (lane == 0) { redSP[w] = sp; redSQ[w] = sq; }
  __syncthreads();
  if (tid == 0) {
    float SP = 0.f, SQ = 0.f;
    for (int ww=0; ww<8; ww++) { SP += redSP[ww]; SQ += redSQ[ww]; }
    float Z = sAb*SP + sCb*SQ;
    float zi = (Z > 0.f) ? 1.f/Z : 0.f;
    g_Ab[row] = sAb*zi;
    g_Cb[row] = sCb*zi;
  }
}

// ---------------- fused masked-softmax attention @ Wh (64x64 output tiles) ----------------
// p entries are already softmax-normalized (A,C pre-divided by Z).
template<int LAYER>
__global__ __launch_bounds__(256) void k_att(const float* __restrict__ masks) {
  __shared__ float pT[64][68];     // p transposed [j][i]
  __shared__ float WhS[64][68];    // Wh tile [j][f]
  __shared__ float s1i[64], Ai[64], Ci[64], s2j[64], Pj[64], Qj[64];
  __shared__ unsigned bw[64][2];
  int b = blockIdx.z, sec = blockIdx.y, it = blockIdx.x;
  int i0 = it*64;
  int tid = threadIdx.x;
  int tx = tid & 15, ty = tid >> 4;
  int pi = tid & 63, pg = tid >> 6;
  const float* Wh = (LAYER==1) ? g_Wh1 : g_Wh2;
  const int ldw   = (LAYER==1) ? 512 : 128;
  const int coff  = sec*64;
  if (tid < 64) {
    int node = b*NN + i0 + tid;
    int si = (LAYER==1) ? node*NH + sec : node;
    s1i[tid] = (LAYER==1) ? g_s1a[si] : g_s1b[si];
    Ai[tid]  = (LAYER==1) ? g_Aa[si]  : g_Ab[si];
    Ci[tid]  = (LAYER==1) ? g_Ca[si]  : g_Cb[si];
  }
  float acc[4][4] = {};
  for (int jt = 0; jt < 8; jt++) {
    __syncthreads();
#pragma unroll
    for (int r = 0; r < 4; r++) {
      int j = (tid >> 4) + r*16;
      float4 v = *(const float4*)(Wh + (size_t)(b*NN + jt*64 + j)*ldw + coff + tx*4);
      *(float4*)&WhS[j][tx*4] = v;
    }
    if (tid < 64) {
      int node = b*NN + jt*64 + tid;
      int si = (LAYER==1) ? node*NH + sec : node;
      s2j[tid] = (LAYER==1) ? g_s2a[si] : g_s2b[si];
      Pj[tid]  = (LAYER==1) ? g_Pa[si]  : g_Pb[si];
      Qj[tid]  = (LAYER==1) ? g_Qa[si]  : g_Qb[si];
    }
    if (tid < 128) {
      bw[tid>>1][tid&1] =
        g_bits[(size_t)(b*NN + i0 + (tid>>1))*NWRD + jt*2 + (tid&1)];
    }
    __syncthreads();
    // generate normalized p tile (transposed)
    {
      float ms1 = s1i[pi], mA = Ai[pi], mC = Ci[pi];
      unsigned wrd = (pg < 2) ? bw[pi][0] : bw[pi][1];
      int jb = pg*16;
#pragma unroll
      for (int q = 0; q < 16; q++) {
        int j = jb + q;
        float p = 0.f;
        if ((wrd >> (j & 31)) & 1u) {
          float sv = ms1 + s2j[j];
          p = (sv > 0.f) ? mA*Pj[j] : mC*Qj[j];
        }
        pT[j][pi] = p;
      }
    }
    __syncthreads();
#pragma unroll 16
    for (int jj = 0; jj < 64; jj++) {
      float4 av = *(float4*)&pT[jj][ty*4];
      float4 bv = *(float4*)&WhS[jj][tx*4];
      float a_[4] = {av.x,av.y,av.z,av.w};
      float b_[4] = {bv.x,bv.y,bv.z,bv.w};
#pragma unroll
      for (int i=0;i<4;i++)
#pragma unroll
        for (int j=0;j<4;j++) acc[i][j] = fmaf(a_[i], b_[j], acc[i][j]);
    }
  }
  float* outp = (LAYER==1) ? g_x1 : g_att2;
  const int ldo = (LAYER==1) ? 512 : 128;
#pragma unroll
  for (int i = 0; i < 4; i++) {
    int ii = ty*4 + i;
    float mk = masks[b*NN + i0 + ii];
    float scale = (LAYER==1) ? mk : mk*mk;
    float v[4];
#pragma unroll
    for (int j=0;j<4;j++) {
      float x = acc[i][j]*scale;
      if (LAYER==1) x = (x > 0.f) ? x : expm1f(x);   // ELU
      v[j] = x;
    }
    *(float4*)(outp + (size_t)(b*NN + i0 + ii)*ldo + coff + tx*4) =
        make_float4(v[0],v[1],v[2],v[3]);
  }
}

// ---------------- node select + 3-layer MLP + softmax ----------------
// node_order dtype sniff: reference declares int64 but JAX default (x64 off)
// yields int32. If int64, buffer = pairs (low,0); all odd int32 slots of the
// first 32 are 0 (values < 512). For genuine int32, 16 uniform values in
// [0,512) are all-zero with prob (1/512)^16 ~ 0.
__global__ __launch_bounds__(256) void k_mlp(
    const int* __restrict__ node_order_i32,
    const float* __restrict__ work, const float* __restrict__ sub,
    const float* __restrict__ w1, const float* __restrict__ b1,
    const float* __restrict__ w2, const float* __restrict__ b2,
    const float* __restrict__ w3, const float* __restrict__ b3,
    float* __restrict__ out) {
  __shared__ float inf[192];
  __shared__ float h1[256];
  __shared__ float h2[256];
  __shared__ float red[8];
  __shared__ float sval;
  __shared__ int snd;
  int b = blockIdx.x, t = threadIdx.x;
  if (t == 0) {
    bool is64 = true;
    for (int i = 1; i < 32; i += 2) is64 = is64 && (node_order_i32[i] == 0);
    snd = is64 ? node_order_i32[2*b] : node_order_i32[b];
  }
  __syncthreads();
  int nd = snd;
  const float* sel = g_att2 + ((size_t)b*NN + nd)*128;
  if (t < 128)       inf[t] = sel[t];
  else if (t < 160)  inf[t] = work[b*32 + (t-128)];
  else if (t < 192)  inf[t] = sub[b*32 + (t-160)];
  __syncthreads();
  float s = b1[t];
  for (int k=0;k<192;k++) s = fmaf(inf[k], w1[k*256+t], s);
  h1[t] = fmaxf(s, 0.f);
  __syncthreads();
  s = b2[t];
  for (int k=0;k<256;k++) s = fmaf(h1[k], w2[k*256+t], s);
  h2[t] = fmaxf(s, 0.f);
  __syncthreads();
  float s0 = b3[t], s1 = b3[256+t];
  for (int k=0;k<256;k++) {
    float h = h2[k];
    s0 = fmaf(h, w3[k*512+t], s0);
    s1 = fmaf(h, w3[k*512+256+t], s1);
  }
  float mx = fmaxf(s0, s1);
  for (int d=16; d; d>>=1) mx = fmaxf(mx, __shfl_xor_sync(0xffffffffu, mx, d));
  if ((t&31)==0) red[t>>5] = mx;
  __syncthreads();
  if (t == 0) { float m = red[0]; for (int i=1;i<8;i++) m = fmaxf(m, red[i]); sval = m; }
  __syncthreads();
  float m = sval;
  float e0 = __expf(s0 - m), e1 = __expf(s1 - m);
  float ps = e0 + e1;
  for (int d=16; d; d>>=1) ps += __shfl_xor_sync(0xffffffffu, ps, d);
  if ((t&31)==0) red[t>>5] = ps;
  __syncthreads();
  if (t == 0) { float q = 0.f; for (int i=0;i<8;i++) q += red[i]; sval = q; }
  __syncthreads();
  float inv = 1.f / sval;
  out[b*512 + t]       = e0*inv;
  out[b*512 + 256 + t] = e1*inv;
}

// ---------------- launcher ----------------
extern "C" void kernel_launch(void* const* d_in, const int* in_sizes, int n_in,
                              void* d_out, int out_size) {
  const float* graph_inf  = (const float*)d_in[0];
  const int*   adj        = (const int*)d_in[1];
  const float* masks      = (const float*)d_in[2];
  const int*   node_order = (const int*)d_in[3];
  const float* work       = (const float*)d_in[4];
  const float* subtask    = (const float*)d_in[5];
  const float* W_heads    = (const float*)d_in[6];
  const float* a_heads    = (const float*)d_in[7];
  const float* W_out      = (const float*)d_in[8];
  const float* a_out      = (const float*)d_in[9];
  const float* fc1w       = (const float*)d_in[10];
  const float* fc1b       = (const float*)d_in[11];
  const float* fc2w       = (const float*)d_in[12];
  const float* fc2b       = (const float*)d_in[13];
  const float* fc3w       = (const float*)d_in[14];
  const float* fc3b       = (const float*)d_in[15];
  float* out = (float*)d_out;
  (void)in_sizes; (void)n_in; (void)out_size;

  k_bits<<<BB*NN, 64>>>(adj);
  k_proj<128,1><<<dim3(BB*NN/64, 8), 256>>>(graph_inf, W_heads);
  k_scores1<<<BB*NN, 256>>>(a_heads);
  k_rowmax1<<<BB*NN, 256>>>();
  k_att<1><<<dim3(NN/64, 8, BB), 256>>>(masks);
  k_proj<512,2><<<dim3(BB*NN/64, 2), 256>>>(nullptr, W_out);
  k_scores2<<<BB*NN/8, 256>>>(a_out);
  k_rowmax2<<<BB*NN, 256>>>();
  k_att<2><<<dim3(NN/64, 2, BB), 256>>>(masks);
  k_mlp<<<BB, 256>>>(node_order, work, subtask,
                     fc1w, fc1b, fc2w, fc2b, fc3w, fc3b, out);
}

// round 5
// speedup vs baseline: 1.3531x; 1.3531x over previous
#include <cuda_runtime.h>
#include <math.h>

#define BB 32
#define NN 512
#define NH 8
#define NWRD 16   // 512/32 bitmask words per adjacency row

typedef unsigned long long u64t;

// packed f32x2 helpers (FFMA2 is PTX-only: fma.rn.f32x2)
__device__ __forceinline__ u64t ffma2(u64t a, u64t b, u64t c) {
  u64t d; asm("fma.rn.f32x2 %0, %1, %2, %3;" : "=l"(d) : "l"(a), "l"(b), "l"(c));
  return d;
}
__device__ __forceinline__ u64t bcast2(float x) {
  u64t d; asm("mov.b64 %0, {%1, %1};" : "=l"(d) : "f"(x));
  return d;
}
__device__ __forceinline__ float2 unpk(u64t d) {
  float2 r; asm("mov.b64 {%0, %1}, %2;" : "=f"(r.x), "=f"(r.y) : "l"(d));
  return r;
}

// ---------------- scratch (device globals; no allocations) ----------------
__device__ unsigned g_bits[BB*NN*NWRD];          // adjacency bitmask
__device__ float g_Wh1[BB*NN*512];               // layer1 per-head projections (concat)
__device__ float g_x1 [BB*NN*512];               // layer1 output (ELU'd concat)
__device__ float g_Wh2[BB*NN*128];               // layer2 projection
__device__ float g_att2[BB*NN*128];              // layer2 GAT output
// per-(node,head) layer1 score factors: A=exp(s1), C=exp(.2 s1), P=exp(s2), Q=exp(.2 s2)
__device__ float g_s1a[BB*NN*NH], g_s2a[BB*NN*NH];
__device__ float g_Aa [BB*NN*NH], g_Ca [BB*NN*NH];
__device__ float g_Pa [BB*NN*NH], g_Qa [BB*NN*NH];
// per-node layer2 score factors
__device__ float g_s1b[BB*NN], g_s2b[BB*NN];
__device__ float g_Ab [BB*NN], g_Cb [BB*NN];
__device__ float g_Pb [BB*NN], g_Qb [BB*NN];

// ---------------- adjacency bitmask ----------------
__global__ void k_bits(const int* __restrict__ adj) {
  int row = blockIdx.x;                      // b*NN + i
  const int* a = adj + (size_t)row*NN;
  int lane = threadIdx.x & 31, w = threadIdx.x >> 5;
  for (int c = w; c < NWRD; c += 2) {
    unsigned m = __ballot_sync(0xffffffffu, a[c*32 + lane] > 0);
    if (lane == 0) g_bits[row*NWRD + c] = m;
  }
}

// ---------------- projection SGEMM (f32x2 core): 64x64 tiles ----------------
// MODE 1: A=graph_inf (K=128), B=W_heads [h][f][o] -> col h*64+o, C=g_Wh1 (ldc 512)
// MODE 2: A=g_x1 (K=512),      B=W_out [512,128],                 C=g_Wh2 (ldc 128)
template<int K, int MODE>
__global__ __launch_bounds__(256) void k_proj(const float* __restrict__ Ain,
                                              const float* __restrict__ Bsrc) {
  __shared__ float As[16][68];
  __shared__ float Bs[16][68];
  const float* A = (MODE==1) ? Ain : g_x1;
  float* C = (MODE==1) ? g_Wh1 : g_Wh2;
  const int ldc = (MODE==1) ? 512 : 128;
  int m0 = blockIdx.x*64, n0 = blockIdx.y*64;
  int tid = threadIdx.x, tx = tid & 15, ty = tid >> 4;
  u64t acc2[2][4];
#pragma unroll
  for (int i=0;i<2;i++)
#pragma unroll
    for (int j=0;j<4;j++) acc2[i][j] = 0ull;
  for (int k0 = 0; k0 < K; k0 += 16) {
    {
      int m = tid >> 2, kq = (tid & 3) * 4;
      float4 v = *(const float4*)(A + (size_t)(m0+m)*K + k0 + kq);
      As[kq+0][m]=v.x; As[kq+1][m]=v.y; As[kq+2][m]=v.z; As[kq+3][m]=v.w;
    }
    {
      int k = tid >> 4, n4 = (tid & 15) * 4;
      float4 v;
      if (MODE==1) {
        int h = n0 >> 6;   // BN=64 aligned to head boundary
        v = *(const float4*)(Bsrc + ((size_t)h*128 + k0 + k)*64 + n4);
      } else {
        v = *(const float4*)(Bsrc + (size_t)(k0+k)*128 + n0 + n4);
      }
      *(float4*)&Bs[k][n4] = v;
    }
    __syncthreads();
#pragma unroll
    for (int kk = 0; kk < 16; kk++) {
      ulonglong2 a2 = *(const ulonglong2*)&As[kk][ty*4];   // (m0,m1),(m2,m3)
      float4 bv = *(const float4*)&Bs[kk][tx*4];
      u64t b0 = bcast2(bv.x), b1 = bcast2(bv.y), b2 = bcast2(bv.z), b3 = bcast2(bv.w);
      acc2[0][0] = ffma2(a2.x, b0, acc2[0][0]);
      acc2[0][1] = ffma2(a2.x, b1, acc2[0][1]);
      acc2[0][2] = ffma2(a2.x, b2, acc2[0][2]);
      acc2[0][3] = ffma2(a2.x, b3, acc2[0][3]);
      acc2[1][0] = ffma2(a2.y, b0, acc2[1][0]);
      acc2[1][1] = ffma2(a2.y, b1, acc2[1][1]);
      acc2[1][2] = ffma2(a2.y, b2, acc2[1][2]);
      acc2[1][3] = ffma2(a2.y, b3, acc2[1][3]);
    }
    __syncthreads();
  }
#pragma unroll
  for (int i2=0;i2<2;i2++) {
    float2 u0 = unpk(acc2[i2][0]), u1 = unpk(acc2[i2][1]);
    float2 u2 = unpk(acc2[i2][2]), u3 = unpk(acc2[i2][3]);
    *(float4*)(C + (size_t)(m0 + ty*4 + 2*i2 + 0)*ldc + n0 + tx*4) =
        make_float4(u0.x,u1.x,u2.x,u3.x);
    *(float4*)(C + (size_t)(m0 + ty*4 + 2*i2 + 1)*ldc + n0 + tx*4) =
        make_float4(u0.y,u1.y,u2.y,u3.y);
  }
}

// ---------------- layer1 scores: s1,s2 per (node,head) + A,C,P,Q ----------------
__global__ __launch_bounds__(256) void k_scores1(const float* __restrict__ a_heads) {
  int row = blockIdx.x;                    // b*NN + n
  int w = threadIdx.x >> 5, l = threadIdx.x & 31;   // warp = head
  const float* wh = g_Wh1 + (size_t)row*512 + w*64;
  const float* ah = a_heads + w*128;
  float s1 = wh[l]*ah[l]    + wh[l+32]*ah[l+32];
  float s2 = wh[l]*ah[64+l] + wh[l+32]*ah[96+l];
  for (int d=16; d; d>>=1) {
    s1 += __shfl_xor_sync(0xffffffffu, s1, d);
    s2 += __shfl_xor_sync(0xffffffffu, s2, d);
  }
  if (l == 0) {
    int idx = row*NH + w;
    g_s1a[idx] = s1; g_s2a[idx] = s2;
    g_Aa[idx] = __expf(s1); g_Ca[idx] = __expf(0.2f*s1);
    g_Pa[idx] = __expf(s2); g_Qa[idx] = __expf(0.2f*s2);
  }
}

// ---------------- layer2 scores ----------------
__global__ __launch_bounds__(256) void k_scores2(const float* __restrict__ a_out) {
  int row = blockIdx.x*8 + (threadIdx.x >> 5);
  int l = threadIdx.x & 31;
  const float* wh = g_Wh2 + (size_t)row*128;
  float s1=0.f, s2=0.f;
#pragma unroll
  for (int r=0;r<4;r++){
    int o=l+r*32; float x=wh[o];
    s1 = fmaf(x, a_out[o], s1);
    s2 = fmaf(x, a_out[128+o], s2);
  }
  for (int d=16; d; d>>=1) {
    s1 += __shfl_xor_sync(0xffffffffu, s1, d);
    s2 += __shfl_xor_sync(0xffffffffu, s2, d);
  }
  if (l==0) {
    g_s1b[row]=s1; g_s2b[row]=s2;
    g_Ab[row]=__expf(s1); g_Cb[row]=__expf(0.2f*s1);
    g_Pb[row]=__expf(s2); g_Qb[row]=__expf(0.2f*s2);
  }
}

// ---------------- fused masked-softmax attention @ Wh (64x64 output tiles) ----------------
// Unnormalized p (A_i P_j | C_i Q_j); row-sum Z accumulated in registers across
// j-tiles, reduced in smem, divided in the epilogue. f32x2 GEMM core.
template<int LAYER>
__global__ __launch_bounds__(256) void k_att(const float* __restrict__ masks) {
  __shared__ float pT[64][68];     // p transposed [j][i]
  __shared__ float WhS[64][68];    // Wh tile [j][f]
  __shared__ float s1i[64], Ai[64], Ci[64], s2j[64], Pj[64], Qj[64];
  __shared__ float part[4][64];
  __shared__ float rsinv[64];
  __shared__ unsigned bw[64][2];
  int b = blockIdx.z, sec = blockIdx.y, it = blockIdx.x;
  int i0 = it*64;
  int tid = threadIdx.x;
  int tx = tid & 15, ty = tid >> 4;
  int pi = tid & 63, pg = tid >> 6;
  const float* Wh = (LAYER==1) ? g_Wh1 : g_Wh2;
  const int ldw   = (LAYER==1) ? 512 : 128;
  const int coff  = sec*64;
  if (tid < 64) {
    int node = b*NN + i0 + tid;
    int si = (LAYER==1) ? node*NH + sec : node;
    s1i[tid] = (LAYER==1) ? g_s1a[si] : g_s1b[si];
    Ai[tid]  = (LAYER==1) ? g_Aa[si]  : g_Ab[si];
    Ci[tid]  = (LAYER==1) ? g_Ca[si]  : g_Cb[si];
  }
  u64t acc2[2][4];
#pragma unroll
  for (int i=0;i<2;i++)
#pragma unroll
    for (int j=0;j<4;j++) acc2[i][j] = 0ull;
  float rsacc = 0.f;
  for (int jt = 0; jt < 8; jt++) {
    __syncthreads();
#pragma unroll
    for (int r = 0; r < 4; r++) {
      int j = (tid >> 4) + r*16;
      float4 v = *(const float4*)(Wh + (size_t)(b*NN + jt*64 + j)*ldw + coff + tx*4);
      *(float4*)&WhS[j][tx*4] = v;
    }
    if (tid < 64) {
      int node = b*NN + jt*64 + tid;
      int si = (LAYER==1) ? node*NH + sec : node;
      s2j[tid] = (LAYER==1) ? g_s2a[si] : g_s2b[si];
      Pj[tid]  = (LAYER==1) ? g_Pa[si]  : g_Pb[si];
      Qj[tid]  = (LAYER==1) ? g_Qa[si]  : g_Qb[si];
    }
    if (tid < 128) {
      bw[tid>>1][tid&1] =
        g_bits[(size_t)(b*NN + i0 + (tid>>1))*NWRD + jt*2 + (tid&1)];
    }
    __syncthreads();
    // generate unnormalized p tile (transposed) + per-thread partial row sum
    {
      float ms1 = s1i[pi], mA = Ai[pi], mC = Ci[pi];
      unsigned wrd = (pg < 2) ? bw[pi][0] : bw[pi][1];
      int jb = pg*16;
#pragma unroll
      for (int q = 0; q < 16; q++) {
        int j = jb + q;
        float p = 0.f;
        if ((wrd >> (j & 31)) & 1u) {
          float sv = ms1 + s2j[j];
          p = (sv > 0.f) ? mA*Pj[j] : mC*Qj[j];
        }
        pT[j][pi] = p;
        rsacc += p;
      }
    }
    __syncthreads();
#pragma unroll 16
    for (int jj = 0; jj < 64; jj++) {
      ulonglong2 a2 = *(const ulonglong2*)&pT[jj][ty*4];   // i-pairs
      float4 bv = *(const float4*)&WhS[jj][tx*4];
      u64t b0 = bcast2(bv.x), b1 = bcast2(bv.y), b2 = bcast2(bv.z), b3 = bcast2(bv.w);
      acc2[0][0] = ffma2(a2.x, b0, acc2[0][0]);
      acc2[0][1] = ffma2(a2.x, b1, acc2[0][1]);
      acc2[0][2] = ffma2(a2.x, b2, acc2[0][2]);
      acc2[0][3] = ffma2(a2.x, b3, acc2[0][3]);
      acc2[1][0] = ffma2(a2.y, b0, acc2[1][0]);
      acc2[1][1] = ffma2(a2.y, b1, acc2[1][1]);
      acc2[1][2] = ffma2(a2.y, b2, acc2[1][2]);
      acc2[1][3] = ffma2(a2.y, b3, acc2[1][3]);
    }
  }
  part[pg][pi] = rsacc;
  __syncthreads();
  if (tid < 64) {
    float z = part[0][tid] + part[1][tid] + part[2][tid] + part[3][tid];
    rsinv[tid] = (z > 0.f) ? 1.f/z : 0.f;
  }
  __syncthreads();
  float* outp = (LAYER==1) ? g_x1 : g_att2;
  const int ldo = (LAYER==1) ? 512 : 128;
#pragma unroll
  for (int i2 = 0; i2 < 2; i2++) {
    float2 u0 = unpk(acc2[i2][0]), u1 = unpk(acc2[i2][1]);
    float2 u2 = unpk(acc2[i2][2]), u3 = unpk(acc2[i2][3]);
    float vlo[4] = {u0.x,u1.x,u2.x,u3.x};
    float vhi[4] = {u0.y,u1.y,u2.y,u3.y};
#pragma unroll
    for (int half = 0; half < 2; half++) {
      int ii = ty*4 + 2*i2 + half;
      float mk = masks[b*NN + i0 + ii];
      float scale = rsinv[ii] * ((LAYER==1) ? mk : mk*mk);
      const float* src = half ? vhi : vlo;
      float v[4];
#pragma unroll
      for (int j=0;j<4;j++) {
        float x = src[j]*scale;
        if (LAYER==1) x = (x > 0.f) ? x : expm1f(x);   // ELU
        v[j] = x;
      }
      *(float4*)(outp + (size_t)(b*NN + i0 + ii)*ldo + coff + tx*4) =
          make_float4(v[0],v[1],v[2],v[3]);
    }
  }
}

// ---------------- node select + 3-layer MLP + softmax ----------------
// node_order dtype sniff: reference declares int64 but JAX default (x64 off)
// yields int32. If int64, odd int32 slots of the first 32 are all 0.
__global__ __launch_bounds__(256) void k_mlp(
    const int* __restrict__ node_order_i32,
    const float* __restrict__ work, const float* __restrict__ sub,
    const float* __restrict__ w1, const float* __restrict__ b1,
    const float* __restrict__ w2, const float* __restrict__ b2,
    const float* __restrict__ w3, const float* __restrict__ b3,
    float* __restrict__ out) {
  __shared__ float inf[192];
  __shared__ float h1[256];
  __shared__ float h2[256];
  __shared__ float red[8];
  __shared__ float sval;
  __shared__ int snd;
  int b = blockIdx.x, t = threadIdx.x;
  if (t == 0) {
    bool is64 = true;
    for (int i = 1; i < 32; i += 2) is64 = is64 && (node_order_i32[i] == 0);
    snd = is64 ? node_order_i32[2*b] : node_order_i32[b];
  }
  __syncthreads();
  int nd = snd;
  const float* sel = g_att2 + ((size_t)b*NN + nd)*128;
  if (t < 128)       inf[t] = sel[t];
  else if (t < 160)  inf[t] = work[b*32 + (t-128)];
  else if (t < 192)  inf[t] = sub[b*32 + (t-160)];
  __syncthreads();
  float s = b1[t];
  for (int k=0;k<192;k++) s = fmaf(inf[k], w1[k*256+t], s);
  h1[t] = fmaxf(s, 0.f);
  __syncthreads();
  s = b2[t];
  for (int k=0;k<256;k++) s = fmaf(h1[k], w2[k*256+t], s);
  h2[t] = fmaxf(s, 0.f);
  __syncthreads();
  float s0 = b3[t], s1 = b3[256+t];
  for (int k=0;k<256;k++) {
    float h = h2[k];
    s0 = fmaf(h, w3[k*512+t], s0);
    s1 = fmaf(h, w3[k*512+256+t], s1);
  }
  float mx = fmaxf(s0, s1);
  for (int d=16; d; d>>=1) mx = fmaxf(mx, __shfl_xor_sync(0xffffffffu, mx, d));
  if ((t&31)==0) red[t>>5] = mx;
  __syncthreads();
  if (t == 0) { float m = red[0]; for (int i=1;i<8;i++) m = fmaxf(m, red[i]); sval = m; }
  __syncthreads();
  float m = sval;
  float e0 = __expf(s0 - m), e1 = __expf(s1 - m);
  float ps = e0 + e1;
  for (int d=16; d; d>>=1) ps += __shfl_xor_sync(0xffffffffu, ps, d);
  if ((t&31)==0) red[t>>5] = ps;
  __syncthreads();
  if (t == 0) { float q = 0.f; for (int i=0;i<8;i++) q += red[i]; sval = q; }
  __syncthreads();
  float inv = 1.f / sval;
  out[b*512 + t]       = e0*inv;
  out[b*512 + 256 + t] = e1*inv;
}

// ---------------- launcher ----------------
extern "C" void kernel_launch(void* const* d_in, const int* in_sizes, int n_in,
                              void* d_out, int out_size) {
  const float* graph_inf  = (const float*)d_in[0];
  const int*   adj        = (const int*)d_in[1];
  const float* masks      = (const float*)d_in[2];
  const int*   node_order = (const int*)d_in[3];
  const float* work       = (const float*)d_in[4];
  const float* subtask    = (const float*)d_in[5];
  const float* W_heads    = (const float*)d_in[6];
  const float* a_heads    = (const float*)d_in[7];
  const float* W_out      = (const float*)d_in[8];
  const float* a_out      = (const float*)d_in[9];
  const float* fc1w       = (const float*)d_in[10];
  const float* fc1b       = (const float*)d_in[11];
  const float* fc2w       = (const float*)d_in[12];
  const float* fc2b       = (const float*)d_in[13];
  const float* fc3w       = (const float*)d_in[14];
  const float* fc3b       = (const float*)d_in[15];
  float* out = (float*)d_out;
  (void)in_sizes; (void)n_in; (void)out_size;

  k_bits<<<BB*NN, 64>>>(adj);
  k_proj<128,1><<<dim3(BB*NN/64, 8), 256>>>(graph_inf, W_heads);
  k_scores1<<<BB*NN, 256>>>(a_heads);
  k_att<1><<<dim3(NN/64, 8, BB), 256>>>(masks);
  k_proj<512,2><<<dim3(BB*NN/64, 2), 256>>>(nullptr, W_out);
  k_scores2<<<BB*NN/8, 256>>>(a_out);
  k_att<2><<<dim3(NN/64, 2, BB), 256>>>(masks);
  k_mlp<<<BB, 256>>>(node_order, work, subtask,
                     fc1w, fc1b, fc2w, fc2b, fc3w, fc3b, out);
}